// round 5
// baseline (speedup 1.0000x reference)
#include <cuda_runtime.h>
#include <cuda_bf16.h>
#include <cfloat>
#include <cstdint>

// Problem constants
#define M_TOK   1024        // B*T = 8*128
#define KDIM    768         // hidden
#define VOC     21128       // vocab
#define MT      128
#define NT      128
#define KT      32
#define NTILES  166         // ceil(21128/128)
#define ASP     36          // As row pitch (floats), 144B-aligned rows
#define BSP     132         // Bs row pitch (floats), 528B-aligned rows

// Scratch (allocation-free): per-(token, n-tile) partial argmax
__device__ float g_pmax[(size_t)M_TOK * NTILES];
__device__ int   g_pidx[(size_t)M_TOK * NTILES];
__device__ int   g_mask_kind;   // 0=u8/bool bytes, 1=int32, 2=float32

// ---------------- f32x2 helpers (Blackwell packed FMA) ----------------
__device__ __forceinline__ unsigned long long ffma2(unsigned long long a,
                                                    unsigned long long b,
                                                    unsigned long long c) {
    unsigned long long d;
    asm("fma.rn.f32x2 %0, %1, %2, %3;" : "=l"(d) : "l"(a), "l"(b), "l"(c));
    return d;
}
__device__ __forceinline__ unsigned long long pack2(float lo, float hi) {
    unsigned long long p;
    asm("mov.b64 %0, {%1, %2};" : "=l"(p) : "f"(lo), "f"(hi));
    return p;
}
__device__ __forceinline__ float2 unpack2(unsigned long long p) {
    float lo, hi;
    asm("mov.b64 {%0, %1}, %2;" : "=f"(lo), "=f"(hi) : "l"(p));
    return make_float2(lo, hi);
}

// ---------------- mask dtype probe ----------------
// bool mask may arrive as 1-byte bool, int32(0/1), or float32(0.0/1.0).
// Inspect the first 21128 bytes (valid under every interpretation):
//   int32 0/1:  nonzero bytes only at pos%4==0
//   f32 0/1.0:  nonzero bytes (0x80,0x3F) only at pos%4 in {2,3}
//   u8 bool:    nonzero bytes at all residues
__global__ void probe_mask_kind(const unsigned char* __restrict__ mb) {
    __shared__ int nz[4];
    if (threadIdx.x < 4) nz[threadIdx.x] = 0;
    __syncthreads();
    for (int i = threadIdx.x; i < VOC; i += blockDim.x)
        if (mb[i]) atomicAdd(&nz[i & 3], 1);
    __syncthreads();
    if (threadIdx.x == 0) {
        int kind = 0;
        if (nz[0] > 0 && nz[1] == 0 && nz[2] == 0 && nz[3] == 0) kind = 1;
        else if (nz[0] == 0 && (nz[2] > 0 || nz[3] > 0))          kind = 2;
        g_mask_kind = kind;
    }
}

// ---------------- fused GEMM (+br +gumbel) -> per-tile argmax ----------------
// C[m,n] = sum_k A[m,k]*Wr[n,k]; tile 128x128, K-step 32, 256 threads,
// 8x8 microtile with f32x2 pairs over m.
__global__ __launch_bounds__(256, 2)
void gemm_argmax(const float* __restrict__ A,   // [1024,768]
                 const float* __restrict__ Wr,  // [21128,768]
                 const float* __restrict__ br,  // [21128]
                 const float* __restrict__ gum) // [1024,21128]
{
    __shared__ float As[MT * ASP];   // [m][k], row pitch 36
    __shared__ float Bs[KT * BSP];   // [k][n], row pitch 132 (transposed)

    const int tid = threadIdx.x;
    const int tx = tid & 15;         // n-direction (16)
    const int ty = tid >> 4;         // m-direction (16)
    const int bx = blockIdx.x;       // n-tile
    const int m0 = blockIdx.y * MT;
    const int n0 = bx * NT;

    unsigned long long acc[4][8];    // pairs over m (lo=even row), 8 n cols
    #pragma unroll
    for (int p = 0; p < 4; p++)
        #pragma unroll
        for (int j = 0; j < 8; j++) acc[p][j] = 0ULL;

    for (int kt = 0; kt < KDIM; kt += KT) {
        // Load A tile: 128x32, 4 float4 per thread, store [m][k]
        #pragma unroll
        for (int r = 0; r < 4; r++) {
            int lin = tid + r * 256;
            int mm = lin >> 3, kq = lin & 7;
            float4 v = *(const float4*)(A + (size_t)(m0 + mm) * KDIM + kt + kq * 4);
            *(float4*)(As + mm * ASP + kq * 4) = v;
        }
        // Load B tile: 128x32, transpose to [k][n]
        #pragma unroll
        for (int r = 0; r < 4; r++) {
            int lin = tid + r * 256;
            int nn = lin >> 3, kq = lin & 7;
            int row = n0 + nn;
            float4 v = make_float4(0.f, 0.f, 0.f, 0.f);
            if (row < VOC)
                v = *(const float4*)(Wr + (size_t)row * KDIM + kt + kq * 4);
            Bs[(kq * 4 + 0) * BSP + nn] = v.x;
            Bs[(kq * 4 + 1) * BSP + nn] = v.y;
            Bs[(kq * 4 + 2) * BSP + nn] = v.z;
            Bs[(kq * 4 + 3) * BSP + nn] = v.w;
        }
        __syncthreads();

        #pragma unroll 8
        for (int kk = 0; kk < KT; kk++) {
            float a[8];
            #pragma unroll
            for (int i = 0; i < 8; i++)
                a[i] = As[(ty * 8 + i) * ASP + kk];  // broadcast across tx
            unsigned long long a2[4];
            #pragma unroll
            for (int p = 0; p < 4; p++) a2[p] = pack2(a[2 * p], a[2 * p + 1]);

            float4 b0 = *(const float4*)(Bs + kk * BSP + tx * 8);
            float4 b1 = *(const float4*)(Bs + kk * BSP + tx * 8 + 4);
            unsigned long long bb[8];
            bb[0] = pack2(b0.x, b0.x); bb[1] = pack2(b0.y, b0.y);
            bb[2] = pack2(b0.z, b0.z); bb[3] = pack2(b0.w, b0.w);
            bb[4] = pack2(b1.x, b1.x); bb[5] = pack2(b1.y, b1.y);
            bb[6] = pack2(b1.z, b1.z); bb[7] = pack2(b1.w, b1.w);

            #pragma unroll
            for (int p = 0; p < 4; p++)
                #pragma unroll
                for (int j = 0; j < 8; j++)
                    acc[p][j] = ffma2(a2[p], bb[j], acc[p][j]);
        }
        __syncthreads();
    }

    // ---- Epilogue: +br +gumbel, argmax over this 128-wide n-tile ----
    const int nb = n0 + tx * 8;                     // VOC % 8 == 0 -> all-or-none
    float brv[8];
    if (nb < VOC) {
        float4 r0 = *(const float4*)(br + nb);
        float4 r1 = *(const float4*)(br + nb + 4);
        brv[0] = r0.x; brv[1] = r0.y; brv[2] = r0.z; brv[3] = r0.w;
        brv[4] = r1.x; brv[5] = r1.y; brv[6] = r1.z; brv[7] = r1.w;
    }

    #pragma unroll
    for (int i = 0; i < 8; i++) {
        const int gm = m0 + ty * 8 + i;
        float mx = -FLT_MAX;
        int   ai = 0x7fffffff;
        if (nb < VOC) {
            const float* gr = gum + (size_t)gm * VOC + nb;
            float4 g0 = *(const float4*)gr;
            float4 g1 = *(const float4*)(gr + 4);
            float gv[8] = {g0.x, g0.y, g0.z, g0.w, g1.x, g1.y, g1.z, g1.w};
            #pragma unroll
            for (int j = 0; j < 8; j++) {
                float2 u = unpack2(acc[i >> 1][j]);
                float v = ((i & 1) ? u.y : u.x) + brv[j] + gv[j];
                if (v > mx) { mx = v; ai = nb + j; }   // strict > keeps first idx
            }
        }
        // Warp butterfly over tx (lanes with same ty share m-rows)
        #pragma unroll
        for (int s = 1; s < 16; s <<= 1) {
            float omx = __shfl_xor_sync(0xffffffffu, mx, s);
            int   oai = __shfl_xor_sync(0xffffffffu, ai, s);
            if (omx > mx || (omx == mx && oai < ai)) { mx = omx; ai = oai; }
        }
        if (tx == 0) {
            g_pmax[(size_t)gm * NTILES + bx] = mx;
            g_pidx[(size_t)gm * NTILES + bx] = ai;
        }
    }
}

// ---------------- final reduce: per-token argmax over tiles, gather, loss ----
__global__ void reduce_loss(const float* __restrict__ sim,
                            const int* __restrict__ ids,
                            const void* __restrict__ mask,
                            float* __restrict__ out, int out_size)
{
    const int t = threadIdx.x;   // 1024 tokens, one block
    float mx = -FLT_MAX;
    int ai = 0;
    const float* pm = g_pmax + (size_t)t * NTILES;
    const int*   pi = g_pidx + (size_t)t * NTILES;
    for (int nt = 0; nt < NTILES; nt++) {
        float v = pm[nt];
        if (v > mx) { mx = v; ai = pi[nt]; }   // ascending tiles -> first max
    }
    const int id = ids[t];
    const int kind = g_mask_kind;
    bool ch;
    if (kind == 1)      ch = ((const int*)mask)[id] != 0;
    else if (kind == 2) ch = ((const float*)mask)[id] != 0.0f;
    else                ch = ((const unsigned char*)mask)[id] != 0;

    float contrib = ch ? (1.0f - sim[(size_t)id * VOC + ai]) : 0.0f;

    __shared__ float red[1024];
    red[t] = contrib;
    __syncthreads();
    for (int s = 512; s > 0; s >>= 1) {
        if (t < s) red[t] += red[t + s];
        __syncthreads();
    }
    if (t == 0) {
        float L = red[0] * (1.0f / 1024.0f);
        for (int k = 0; k < out_size; k++) out[k] = L;
    }
}

extern "C" void kernel_launch(void* const* d_in, const int* in_sizes, int n_in,
                              void* d_out, int out_size) {
    const float* seq  = (const float*)d_in[0];   // [8,128,768]
    const float* Wr   = (const float*)d_in[1];   // [21128,768]
    const float* br   = (const float*)d_in[2];   // [21128]
    const float* sim  = (const float*)d_in[3];   // [21128,21128]
    const float* gum  = (const float*)d_in[4];   // [8,128,21128]
    const int*   ids  = (const int*)d_in[5];     // [8,128]
    const void*  mask = d_in[6];                 // [21128] bool-ish

    probe_mask_kind<<<1, 256>>>((const unsigned char*)mask);

    dim3 grid(NTILES, M_TOK / MT);               // 166 x 8
    gemm_argmax<<<grid, 256>>>(seq, Wr, br, gum);

    reduce_loss<<<1, 1024>>>(sim, ids, mask, (float*)d_out, out_size);
}

// round 6
// speedup vs baseline: 1.0004x; 1.0004x over previous
#include <cuda_runtime.h>
#include <cuda_bf16.h>
#include <cfloat>
#include <cstdint>

// Problem constants
#define M_TOK   1024        // B*T = 8*128
#define KDIM    768         // hidden
#define VOC     21128       // vocab
#define MT      128
#define NT      128
#define KT      32
#define NTILES  166         // ceil(21128/128)
#define ASP     36          // As row pitch (floats), 144B-aligned rows
#define BSP     132         // Bs row pitch (floats), 528B-aligned rows

// Scratch (allocation-free): per-(token, n-tile) partial argmax
__device__ float g_pmax[(size_t)M_TOK * NTILES];
__device__ int   g_pidx[(size_t)M_TOK * NTILES];
__device__ int   g_mask_kind;   // 0=u8/bool bytes, 1=int32, 2=float32

// ---------------- f32x2 helpers (Blackwell packed FMA) ----------------
__device__ __forceinline__ unsigned long long ffma2(unsigned long long a,
                                                    unsigned long long b,
                                                    unsigned long long c) {
    unsigned long long d;
    asm("fma.rn.f32x2 %0, %1, %2, %3;" : "=l"(d) : "l"(a), "l"(b), "l"(c));
    return d;
}
__device__ __forceinline__ unsigned long long pack2(float lo, float hi) {
    unsigned long long p;
    asm("mov.b64 %0, {%1, %2};" : "=l"(p) : "f"(lo), "f"(hi));
    return p;
}
__device__ __forceinline__ float2 unpack2(unsigned long long p) {
    float lo, hi;
    asm("mov.b64 {%0, %1}, %2;" : "=f"(lo), "=f"(hi) : "l"(p));
    return make_float2(lo, hi);
}

// ---------------- mask dtype probe ----------------
// bool mask may arrive as 1-byte bool, int32(0/1), or float32(0.0/1.0).
// Inspect the first 21128 bytes (valid under every interpretation):
//   int32 0/1:  nonzero bytes only at pos%4==0
//   f32 0/1.0:  nonzero bytes (0x80,0x3F) only at pos%4 in {2,3}
//   u8 bool:    nonzero bytes at all residues
__global__ void probe_mask_kind(const unsigned char* __restrict__ mb) {
    __shared__ int nz[4];
    if (threadIdx.x < 4) nz[threadIdx.x] = 0;
    __syncthreads();
    for (int i = threadIdx.x; i < VOC; i += blockDim.x)
        if (mb[i]) atomicAdd(&nz[i & 3], 1);
    __syncthreads();
    if (threadIdx.x == 0) {
        int kind = 0;
        if (nz[0] > 0 && nz[1] == 0 && nz[2] == 0 && nz[3] == 0) kind = 1;
        else if (nz[0] == 0 && (nz[2] > 0 || nz[3] > 0))          kind = 2;
        g_mask_kind = kind;
    }
}

// ---------------- fused GEMM (+br +gumbel) -> per-tile argmax ----------------
// C[m,n] = sum_k A[m,k]*Wr[n,k]; tile 128x128, K-step 32, 256 threads,
// 8x8 microtile with f32x2 pairs over m.
__global__ __launch_bounds__(256, 2)
void gemm_argmax(const float* __restrict__ A,   // [1024,768]
                 const float* __restrict__ Wr,  // [21128,768]
                 const float* __restrict__ br,  // [21128]
                 const float* __restrict__ gum) // [1024,21128]
{
    __shared__ float As[MT * ASP];   // [m][k], row pitch 36
    __shared__ float Bs[KT * BSP];   // [k][n], row pitch 132 (transposed)

    const int tid = threadIdx.x;
    const int tx = tid & 15;         // n-direction (16)
    const int ty = tid >> 4;         // m-direction (16)
    const int bx = blockIdx.x;       // n-tile
    const int m0 = blockIdx.y * MT;
    const int n0 = bx * NT;

    unsigned long long acc[4][8];    // pairs over m (lo=even row), 8 n cols
    #pragma unroll
    for (int p = 0; p < 4; p++)
        #pragma unroll
        for (int j = 0; j < 8; j++) acc[p][j] = 0ULL;

    for (int kt = 0; kt < KDIM; kt += KT) {
        // Load A tile: 128x32, 4 float4 per thread, store [m][k]
        #pragma unroll
        for (int r = 0; r < 4; r++) {
            int lin = tid + r * 256;
            int mm = lin >> 3, kq = lin & 7;
            float4 v = *(const float4*)(A + (size_t)(m0 + mm) * KDIM + kt + kq * 4);
            *(float4*)(As + mm * ASP + kq * 4) = v;
        }
        // Load B tile: 128x32, transpose to [k][n]
        #pragma unroll
        for (int r = 0; r < 4; r++) {
            int lin = tid + r * 256;
            int nn = lin >> 3, kq = lin & 7;
            int row = n0 + nn;
            float4 v = make_float4(0.f, 0.f, 0.f, 0.f);
            if (row < VOC)
                v = *(const float4*)(Wr + (size_t)row * KDIM + kt + kq * 4);
            Bs[(kq * 4 + 0) * BSP + nn] = v.x;
            Bs[(kq * 4 + 1) * BSP + nn] = v.y;
            Bs[(kq * 4 + 2) * BSP + nn] = v.z;
            Bs[(kq * 4 + 3) * BSP + nn] = v.w;
        }
        __syncthreads();

        #pragma unroll 8
        for (int kk = 0; kk < KT; kk++) {
            float a[8];
            #pragma unroll
            for (int i = 0; i < 8; i++)
                a[i] = As[(ty * 8 + i) * ASP + kk];  // broadcast across tx
            unsigned long long a2[4];
            #pragma unroll
            for (int p = 0; p < 4; p++) a2[p] = pack2(a[2 * p], a[2 * p + 1]);

            float4 b0 = *(const float4*)(Bs + kk * BSP + tx * 8);
            float4 b1 = *(const float4*)(Bs + kk * BSP + tx * 8 + 4);
            unsigned long long bb[8];
            bb[0] = pack2(b0.x, b0.x); bb[1] = pack2(b0.y, b0.y);
            bb[2] = pack2(b0.z, b0.z); bb[3] = pack2(b0.w, b0.w);
            bb[4] = pack2(b1.x, b1.x); bb[5] = pack2(b1.y, b1.y);
            bb[6] = pack2(b1.z, b1.z); bb[7] = pack2(b1.w, b1.w);

            #pragma unroll
            for (int p = 0; p < 4; p++)
                #pragma unroll
                for (int j = 0; j < 8; j++)
                    acc[p][j] = ffma2(a2[p], bb[j], acc[p][j]);
        }
        __syncthreads();
    }

    // ---- Epilogue: +br +gumbel, argmax over this 128-wide n-tile ----
    const int nb = n0 + tx * 8;                     // VOC % 8 == 0 -> all-or-none
    float brv[8];
    if (nb < VOC) {
        float4 r0 = *(const float4*)(br + nb);
        float4 r1 = *(const float4*)(br + nb + 4);
        brv[0] = r0.x; brv[1] = r0.y; brv[2] = r0.z; brv[3] = r0.w;
        brv[4] = r1.x; brv[5] = r1.y; brv[6] = r1.z; brv[7] = r1.w;
    }

    #pragma unroll
    for (int i = 0; i < 8; i++) {
        const int gm = m0 + ty * 8 + i;
        float mx = -FLT_MAX;
        int   ai = 0x7fffffff;
        if (nb < VOC) {
            const float* gr = gum + (size_t)gm * VOC + nb;
            float4 g0 = *(const float4*)gr;
            float4 g1 = *(const float4*)(gr + 4);
            float gv[8] = {g0.x, g0.y, g0.z, g0.w, g1.x, g1.y, g1.z, g1.w};
            #pragma unroll
            for (int j = 0; j < 8; j++) {
                float2 u = unpack2(acc[i >> 1][j]);
                float v = ((i & 1) ? u.y : u.x) + brv[j] + gv[j];
                if (v > mx) { mx = v; ai = nb + j; }   // strict > keeps first idx
            }
        }
        // Warp butterfly over tx (lanes with same ty share m-rows)
        #pragma unroll
        for (int s = 1; s < 16; s <<= 1) {
            float omx = __shfl_xor_sync(0xffffffffu, mx, s);
            int   oai = __shfl_xor_sync(0xffffffffu, ai, s);
            if (omx > mx || (omx == mx && oai < ai)) { mx = omx; ai = oai; }
        }
        if (tx == 0) {
            g_pmax[(size_t)gm * NTILES + bx] = mx;
            g_pidx[(size_t)gm * NTILES + bx] = ai;
        }
    }
}

// ---------------- final reduce: per-token argmax over tiles, gather, loss ----
__global__ void reduce_loss(const float* __restrict__ sim,
                            const int* __restrict__ ids,
                            const void* __restrict__ mask,
                            float* __restrict__ out, int out_size)
{
    const int t = threadIdx.x;   // 1024 tokens, one block
    float mx = -FLT_MAX;
    int ai = 0;
    const float* pm = g_pmax + (size_t)t * NTILES;
    const int*   pi = g_pidx + (size_t)t * NTILES;
    for (int nt = 0; nt < NTILES; nt++) {
        float v = pm[nt];
        if (v > mx) { mx = v; ai = pi[nt]; }   // ascending tiles -> first max
    }
    const int id = ids[t];
    const int kind = g_mask_kind;
    bool ch;
    if (kind == 1)      ch = ((const int*)mask)[id] != 0;
    else if (kind == 2) ch = ((const float*)mask)[id] != 0.0f;
    else                ch = ((const unsigned char*)mask)[id] != 0;

    float contrib = ch ? (1.0f - sim[(size_t)id * VOC + ai]) : 0.0f;

    __shared__ float red[1024];
    red[t] = contrib;
    __syncthreads();
    for (int s = 512; s > 0; s >>= 1) {
        if (t < s) red[t] += red[t + s];
        __syncthreads();
    }
    if (t == 0) {
        float L = red[0] * (1.0f / 1024.0f);
        for (int k = 0; k < out_size; k++) out[k] = L;
    }
}

extern "C" void kernel_launch(void* const* d_in, const int* in_sizes, int n_in,
                              void* d_out, int out_size) {
    const float* seq  = (const float*)d_in[0];   // [8,128,768]
    const float* Wr   = (const float*)d_in[1];   // [21128,768]
    const float* br   = (const float*)d_in[2];   // [21128]
    const float* sim  = (const float*)d_in[3];   // [21128,21128]
    const float* gum  = (const float*)d_in[4];   // [8,128,21128]
    const int*   ids  = (const int*)d_in[5];     // [8,128]
    const void*  mask = d_in[6];                 // [21128] bool-ish

    probe_mask_kind<<<1, 256>>>((const unsigned char*)mask);

    dim3 grid(NTILES, M_TOK / MT);               // 166 x 8
    gemm_argmax<<<grid, 256>>>(seq, Wr, br, gum);

    reduce_loss<<<1, 1024>>>(sim, ids, mask, (float*)d_out, out_size);
}

// round 8
// speedup vs baseline: 2.7419x; 2.7408x over previous
#include <cuda_runtime.h>
#include <cuda_bf16.h>
#include <cfloat>
#include <cstdint>

// ---------------- problem constants ----------------
#define M_TOK   1024
#define KDIM    768
#define VOC     21128
#define VP      21248          // padded vocab: 166 * 128
#define NT2     166            // n-tiles of 128
#define BM      128
#define BN      128
#define BK      32
#define NKT     24             // 768/32
#define NSTG    3

// smem: per stage: Ahi 8K | Alo 8K | Bhi 8K | Blo 8K = 32 KB
#define STG_BYTES 32768
#define R_ALO     8192
#define R_BHI     16384
#define R_BLO     24576
#define SM_EPI    (NSTG * STG_BYTES)        // 98304: epilogue pm/pi
#define SM_TOTAL_G (SM_EPI + 128*4*4 + 128*4*4)   // +4096 = 102400

// ---------------- device scratch (allocation-free) ----------------
__device__ __nv_bfloat16 g_Whi[(size_t)VP * KDIM];
__device__ __nv_bfloat16 g_Wlo[(size_t)VP * KDIM];
__device__ __nv_bfloat16 g_Ahi[(size_t)M_TOK * KDIM];
__device__ __nv_bfloat16 g_Alo[(size_t)M_TOK * KDIM];
__device__ float g_pmax[(size_t)M_TOK * NT2];
__device__ int   g_pidx[(size_t)M_TOK * NT2];
__device__ int   g_mask_kind;

// ---------------- PTX helpers (all portable, no 'a'-feature) ----------------
__device__ __forceinline__ uint32_t smem_u32(const void* p) {
    uint32_t a;
    asm("{ .reg .u64 t; cvta.to.shared.u64 t, %1; cvt.u32.u64 %0, t; }" : "=r"(a) : "l"(p));
    return a;
}
__device__ __forceinline__ void cp16(uint32_t dst, const void* src) {
    asm volatile("cp.async.cg.shared.global [%0], [%1], 16;" :: "r"(dst), "l"(src));
}
__device__ __forceinline__ void cp_commit() {
    asm volatile("cp.async.commit_group;" ::: "memory");
}
template <int N>
__device__ __forceinline__ void cp_wait() {
    asm volatile("cp.async.wait_group %0;" :: "n"(N) : "memory");
}
__device__ __forceinline__ void ldsm_x4(uint32_t* r, uint32_t addr) {
    asm volatile("ldmatrix.sync.aligned.m8n8.x4.shared.b16 {%0,%1,%2,%3}, [%4];"
                 : "=r"(r[0]), "=r"(r[1]), "=r"(r[2]), "=r"(r[3]) : "r"(addr));
}
__device__ __forceinline__ void mma16816(float* c, const uint32_t* a, const uint32_t* b) {
    asm volatile(
        "mma.sync.aligned.m16n8k16.row.col.f32.bf16.bf16.f32 "
        "{%0,%1,%2,%3}, {%4,%5,%6,%7}, {%8,%9}, {%0,%1,%2,%3};"
        : "+f"(c[0]), "+f"(c[1]), "+f"(c[2]), "+f"(c[3])
        : "r"(a[0]), "r"(a[1]), "r"(a[2]), "r"(a[3]), "r"(b[0]), "r"(b[1]));
}
__device__ __forceinline__ uint32_t sw64(uint32_t b) { return b ^ ((b >> 3) & 0x30); }

__device__ __forceinline__ uint32_t packbf2(float x, float y) {
    __nv_bfloat162 h;
    h.x = __float2bfloat16(x);
    h.y = __float2bfloat16(y);
    return *(uint32_t*)&h;
}

// ---------------- mask dtype probe ----------------
__global__ void probe_mask_kind(const unsigned char* __restrict__ mb) {
    __shared__ int nz[4];
    if (threadIdx.x < 4) nz[threadIdx.x] = 0;
    __syncthreads();
    for (int i = threadIdx.x; i < VOC; i += blockDim.x)
        if (mb[i]) atomicAdd(&nz[i & 3], 1);
    __syncthreads();
    if (threadIdx.x == 0) {
        int kind = 0;
        if (nz[0] > 0 && nz[1] == 0 && nz[2] == 0 && nz[3] == 0) kind = 1;
        else if (nz[0] == 0 && (nz[2] > 0 || nz[3] > 0))          kind = 2;
        g_mask_kind = kind;
    }
}

// ---------------- pre-pass: split f32 -> bf16 hi/lo ----------------
__global__ void convert_split(const float* __restrict__ A, const float* __restrict__ W) {
    const size_t nW4 = (size_t)VP * KDIM / 4;
    const size_t nA4 = (size_t)M_TOK * KDIM / 4;
    const size_t nV4 = (size_t)VOC * KDIM / 4;
    for (size_t i = (size_t)blockIdx.x * blockDim.x + threadIdx.x;
         i < nW4 + nA4; i += (size_t)gridDim.x * blockDim.x) {
        float4 v;
        __nv_bfloat16 *hd, *ld;
        if (i < nW4) {
            size_t e = i * 4;
            v = (i < nV4) ? *(const float4*)(W + e) : make_float4(0.f, 0.f, 0.f, 0.f);
            hd = g_Whi + e; ld = g_Wlo + e;
        } else {
            size_t e = (i - nW4) * 4;
            v = *(const float4*)(A + e);
            hd = g_Ahi + e; ld = g_Alo + e;
        }
        float hx = __bfloat162float(__float2bfloat16(v.x));
        float hy = __bfloat162float(__float2bfloat16(v.y));
        float hz = __bfloat162float(__float2bfloat16(v.z));
        float hw = __bfloat162float(__float2bfloat16(v.w));
        uint2 hp, lp;
        hp.x = packbf2(v.x, v.y);        hp.y = packbf2(v.z, v.w);
        lp.x = packbf2(v.x - hx, v.y - hy);
        lp.y = packbf2(v.z - hz, v.w - hw);
        *(uint2*)hd = hp;
        *(uint2*)ld = lp;
    }
}

// ---------------- stage loader ----------------
__device__ __forceinline__ void load_stage(uint32_t sb, int buf, int m0, int n0,
                                           int kt, int tid) {
    uint32_t base = sb + buf * STG_BYTES;
    #pragma unroll
    for (int i = 0; i < 2; i++) {
        int id = tid + i * 256;
        int row = id >> 2, c = id & 3;           // 128 rows x 4 x 16B chunks
        uint32_t so = sw64(row * 64 + c * 16);
        size_t ao = (size_t)(m0 + row) * KDIM + kt + c * 8;
        size_t bo = (size_t)(n0 + row) * KDIM + kt + c * 8;
        cp16(base + so,         g_Ahi + ao);
        cp16(base + R_ALO + so, g_Alo + ao);
        cp16(base + R_BHI + so, g_Whi + bo);
        cp16(base + R_BLO + so, g_Wlo + bo);
    }
}

// ---------------- stage compute: 2 x k16, 48 HMMA per warp ----------------
__device__ __forceinline__ void compute_stage(uint32_t sb, int buf, int lane,
                                              int wm, int wn, float acc[4][4][4]) {
    uint32_t base = sb + buf * STG_BYTES;
    #pragma unroll
    for (int kk = 0; kk < 2; kk++) {
        uint32_t ah[4][4], al[4][4], bh[2][4], bl[2][4];
        #pragma unroll
        for (int mi = 0; mi < 4; mi++) {
            int row = wm * 64 + mi * 16 + (lane & 15);
            uint32_t off = sw64(row * 64 + kk * 32 + ((lane >> 4) & 1) * 16);
            ldsm_x4(ah[mi], base + off);
            ldsm_x4(al[mi], base + R_ALO + off);
        }
        #pragma unroll
        for (int bi = 0; bi < 2; bi++) {
            int row = wn * 32 + bi * 16 + (lane & 7) + ((lane >> 4) & 1) * 8;
            uint32_t off = sw64(row * 64 + kk * 32 + ((lane >> 3) & 1) * 16);
            ldsm_x4(bh[bi], base + R_BHI + off);
            ldsm_x4(bl[bi], base + R_BLO + off);
        }
        // term 1: Ahi * Bhi
        #pragma unroll
        for (int mi = 0; mi < 4; mi++)
            #pragma unroll
            for (int ni = 0; ni < 4; ni++)
                mma16816(acc[mi][ni], ah[mi], &bh[ni >> 1][(ni & 1) * 2]);
        // term 2: Ahi * Blo
        #pragma unroll
        for (int mi = 0; mi < 4; mi++)
            #pragma unroll
            for (int ni = 0; ni < 4; ni++)
                mma16816(acc[mi][ni], ah[mi], &bl[ni >> 1][(ni & 1) * 2]);
        // term 3: Alo * Bhi
        #pragma unroll
        for (int mi = 0; mi < 4; mi++)
            #pragma unroll
            for (int ni = 0; ni < 4; ni++)
                mma16816(acc[mi][ni], al[mi], &bh[ni >> 1][(ni & 1) * 2]);
    }
}

// ---------------- main GEMM + fused argmax epilogue ----------------
__global__ __launch_bounds__(256, 1)
void gemm_hmma_argmax(const float* __restrict__ br, const float* __restrict__ gum) {
    extern __shared__ char smem[];
    const uint32_t sb = smem_u32(smem);
    const int tid  = threadIdx.x;
    const int lane = tid & 31;
    const int wid  = tid >> 5;
    const int wm   = wid & 1;       // 2 warps over m
    const int wn   = wid >> 1;      // 4 warps over n
    const int m0   = blockIdx.x * BM;   // x fastest: 8 m-CTAs share the B tile
    const int nt   = blockIdx.y;
    const int n0   = nt * BN;

    float acc[4][4][4];
    #pragma unroll
    for (int mi = 0; mi < 4; mi++)
        #pragma unroll
        for (int ni = 0; ni < 4; ni++)
            #pragma unroll
            for (int j = 0; j < 4; j++) acc[mi][ni][j] = 0.f;

    // pipeline prologue
    #pragma unroll
    for (int s = 0; s < NSTG - 1; s++) {
        load_stage(sb, s, m0, n0, s * BK, tid);
        cp_commit();
    }
    // mainloop
    for (int k = 0; k < NKT; k++) {
        int pf = k + NSTG - 1;
        if (pf < NKT) load_stage(sb, pf % NSTG, m0, n0, pf * BK, tid);
        cp_commit();
        cp_wait<NSTG - 1>();
        __syncthreads();
        compute_stage(sb, k % NSTG, lane, wm, wn, acc);
        __syncthreads();
    }

    // ---- epilogue: +br +gumbel, per-row argmax ----
    const int g = lane >> 2, t = lane & 3;
    float* pm = (float*)(smem + SM_EPI);            // [128][4]
    int*   pi = (int*)(smem + SM_EPI + 2048);       // [128][4]

    float2 brv[4];
    bool valid[4];
    #pragma unroll
    for (int ni = 0; ni < 4; ni++) {
        int col = wn * 32 + ni * 8 + 2 * t;
        valid[ni] = (n0 + col) < VOC;               // pairs are all-or-none (VOC even)
        brv[ni] = valid[ni] ? *(const float2*)(br + n0 + col) : make_float2(0.f, 0.f);
    }

    #pragma unroll
    for (int mi = 0; mi < 4; mi++) {
        #pragma unroll
        for (int h = 0; h < 2; h++) {
            int rl = wm * 64 + mi * 16 + g + h * 8;  // row in CTA tile
            const float* gr = gum + (size_t)(m0 + rl) * VOC + n0;
            float mx = -FLT_MAX;
            int   ai = 0x7fffffff;
            #pragma unroll
            for (int ni = 0; ni < 4; ni++) {
                if (valid[ni]) {
                    int col = wn * 32 + ni * 8 + 2 * t;
                    float2 gg = *(const float2*)(gr + col);
                    float v0 = acc[mi][ni][h * 2 + 0] + brv[ni].x + gg.x;
                    float v1 = acc[mi][ni][h * 2 + 1] + brv[ni].y + gg.y;
                    if (v0 > mx) { mx = v0; ai = n0 + col; }
                    if (v1 > mx) { mx = v1; ai = n0 + col + 1; }
                }
            }
            // quad reduce over t (lanes g*4 + t)
            #pragma unroll
            for (int s = 1; s < 4; s <<= 1) {
                float omx = __shfl_xor_sync(0xffffffffu, mx, s);
                int   oai = __shfl_xor_sync(0xffffffffu, ai, s);
                if (omx > mx || (omx == mx && oai < ai)) { mx = omx; ai = oai; }
            }
            if (t == 0) { pm[rl * 4 + wn] = mx; pi[rl * 4 + wn] = ai; }
        }
    }
    __syncthreads();
    if (tid < BM) {
        float mx = -FLT_MAX;
        int   ai = 0x7fffffff;
        #pragma unroll
        for (int w = 0; w < 4; w++) {               // ascending cols -> first idx on tie
            float v = pm[tid * 4 + w];
            if (v > mx) { mx = v; ai = pi[tid * 4 + w]; }
        }
        g_pmax[(size_t)(m0 + tid) * NT2 + nt] = mx;
        g_pidx[(size_t)(m0 + tid) * NT2 + nt] = ai;
    }
}

// ---------------- final reduce: global argmax per token, gather, loss ----------------
__global__ void reduce_loss(const float* __restrict__ sim,
                            const int* __restrict__ ids,
                            const void* __restrict__ mask,
                            float* __restrict__ out, int out_size) {
    const int t = threadIdx.x;   // 1024 tokens, one block
    float mx = -FLT_MAX;
    int ai = 0;
    const float* pm = g_pmax + (size_t)t * NT2;
    const int*   pi = g_pidx + (size_t)t * NT2;
    for (int n = 0; n < NT2; n++) {
        float v = pm[n];
        if (v > mx) { mx = v; ai = pi[n]; }   // ascending tiles -> first max
    }
    const int id = ids[t];
    const int kind = g_mask_kind;
    bool ch;
    if (kind == 1)      ch = ((const int*)mask)[id] != 0;
    else if (kind == 2) ch = ((const float*)mask)[id] != 0.0f;
    else                ch = ((const unsigned char*)mask)[id] != 0;

    float contrib = ch ? (1.0f - sim[(size_t)id * VOC + ai]) : 0.0f;

    __shared__ float red[1024];
    red[t] = contrib;
    __syncthreads();
    for (int s = 512; s > 0; s >>= 1) {
        if (t < s) red[t] += red[t + s];
        __syncthreads();
    }
    if (t == 0) {
        float L = red[0] * (1.0f / 1024.0f);
        for (int k = 0; k < out_size; k++) out[k] = L;
    }
}

extern "C" void kernel_launch(void* const* d_in, const int* in_sizes, int n_in,
                              void* d_out, int out_size) {
    const float* seq  = (const float*)d_in[0];   // [8,128,768]
    const float* Wr   = (const float*)d_in[1];   // [21128,768]
    const float* br   = (const float*)d_in[2];   // [21128]
    const float* sim  = (const float*)d_in[3];   // [21128,21128]
    const float* gum  = (const float*)d_in[4];   // [8,128,21128]
    const int*   ids  = (const int*)d_in[5];     // [8,128]
    const void*  mask = d_in[6];                 // [21128] bool-ish

    static bool attr_set = false;
    if (!attr_set) {
        cudaFuncSetAttribute(gemm_hmma_argmax,
                             cudaFuncAttributeMaxDynamicSharedMemorySize, SM_TOTAL_G);
        attr_set = true;
    }

    probe_mask_kind<<<1, 256>>>((const unsigned char*)mask);
    convert_split<<<2048, 256>>>(seq, Wr);

    dim3 grid(M_TOK / BM, NT2);   // (8, 166); x fastest -> B tile shared in L2
    gemm_hmma_argmax<<<grid, 256, SM_TOTAL_G>>>(br, gum);

    reduce_loss<<<1, 1024>>>(sim, ids, mask, (float*)d_out, out_size);
}

// round 9
// speedup vs baseline: 5.4703x; 1.9951x over previous
#include <cuda_runtime.h>
#include <cuda_bf16.h>
#include <cfloat>
#include <cstdint>

// ---------------- problem constants ----------------
#define M_TOK   1024
#define KDIM    768
#define VOC     21128
#define VP      21248          // padded vocab: 166 * 128
#define NT2     166            // n-tiles of 128
#define BM      128
#define BN      128
#define BK      64
#define NKT     12             // 768/64
#define NSTG    3
#define THETA   0.02f          // rescue threshold (~22 sigma of bf16 dot error)

// smem per stage: A 16K | B 16K
#define STG_BYTES 32768
#define R_B       16384
#define SM_TOTAL_G (NSTG * STG_BYTES)   // 98304 (epilogue reuses stage 0)

// ---------------- device scratch (allocation-free) ----------------
__device__ __nv_bfloat16 g_Wbf[(size_t)VP * KDIM];
__device__ __nv_bfloat16 g_Abf[(size_t)M_TOK * KDIM];
__device__ float g_p1v[(size_t)M_TOK * NT2];
__device__ int   g_p1i[(size_t)M_TOK * NT2];
__device__ float g_p2v[(size_t)M_TOK * NT2];
__device__ int   g_p2i[(size_t)M_TOK * NT2];
__device__ float g_contrib[M_TOK];
__device__ int   g_mask_kind;

// ---------------- PTX helpers (portable, no 'a'-feature) ----------------
__device__ __forceinline__ uint32_t smem_u32(const void* p) {
    uint32_t a;
    asm("{ .reg .u64 t; cvta.to.shared.u64 t, %1; cvt.u32.u64 %0, t; }" : "=r"(a) : "l"(p));
    return a;
}
__device__ __forceinline__ void cp16(uint32_t dst, const void* src) {
    asm volatile("cp.async.cg.shared.global [%0], [%1], 16;" :: "r"(dst), "l"(src));
}
__device__ __forceinline__ void cp_commit() {
    asm volatile("cp.async.commit_group;" ::: "memory");
}
template <int N>
__device__ __forceinline__ void cp_wait() {
    asm volatile("cp.async.wait_group %0;" :: "n"(N) : "memory");
}
__device__ __forceinline__ void ldsm_x4(uint32_t* r, uint32_t addr) {
    asm volatile("ldmatrix.sync.aligned.m8n8.x4.shared.b16 {%0,%1,%2,%3}, [%4];"
                 : "=r"(r[0]), "=r"(r[1]), "=r"(r[2]), "=r"(r[3]) : "r"(addr));
}
__device__ __forceinline__ void mma16816(float* c, const uint32_t* a, const uint32_t* b) {
    asm volatile(
        "mma.sync.aligned.m16n8k16.row.col.f32.bf16.bf16.f32 "
        "{%0,%1,%2,%3}, {%4,%5,%6,%7}, {%8,%9}, {%0,%1,%2,%3};"
        : "+f"(c[0]), "+f"(c[1]), "+f"(c[2]), "+f"(c[3])
        : "r"(a[0]), "r"(a[1]), "r"(a[2]), "r"(a[3]), "r"(b[0]), "r"(b[1]));
}
__device__ __forceinline__ uint32_t sw128(uint32_t b) { return b ^ ((b >> 3) & 0x70); }

__device__ __forceinline__ uint32_t packbf2(float x, float y) {
    __nv_bfloat162 h;
    h.x = __float2bfloat16(x);
    h.y = __float2bfloat16(y);
    return *(uint32_t*)&h;
}

// top-2 merge keeping first-occurrence (min idx) semantics
__device__ __forceinline__ void top2_merge(float v, int i, float& m1, int& i1,
                                           float& m2, int& i2) {
    if (v > m1 || (v == m1 && i < i1)) {
        m2 = m1; i2 = i1; m1 = v; i1 = i;
    } else if (v > m2 || (v == m2 && i < i2)) {
        m2 = v; i2 = i;
    }
}

// ---------------- mask dtype probe (no hot atomics) ----------------
__global__ void probe_mask_kind(const unsigned char* __restrict__ mb) {
    __shared__ int nz[4];
    if (threadIdx.x < 4) nz[threadIdx.x] = 0;
    __syncthreads();
    int c[4] = {0, 0, 0, 0};
    for (int i = threadIdx.x; i < VOC; i += blockDim.x)
        if (mb[i]) c[i & 3]++;
    #pragma unroll
    for (int r = 0; r < 4; r++)
        if (c[r]) atomicAdd(&nz[r], c[r]);
    __syncthreads();
    if (threadIdx.x == 0) {
        int kind = 0;
        if (nz[0] > 0 && nz[1] == 0 && nz[2] == 0 && nz[3] == 0) kind = 1;
        else if (nz[0] == 0 && (nz[2] > 0 || nz[3] > 0))          kind = 2;
        g_mask_kind = kind;
    }
}

// ---------------- pre-pass: f32 -> bf16 (hi only) ----------------
__global__ void convert_bf16(const float* __restrict__ A, const float* __restrict__ W) {
    const size_t nW4 = (size_t)VP * KDIM / 4;
    const size_t nA4 = (size_t)M_TOK * KDIM / 4;
    const size_t nV4 = (size_t)VOC * KDIM / 4;
    for (size_t i = (size_t)blockIdx.x * blockDim.x + threadIdx.x;
         i < nW4 + nA4; i += (size_t)gridDim.x * blockDim.x) {
        float4 v;
        __nv_bfloat16* dst;
        if (i < nW4) {
            size_t e = i * 4;
            v = (i < nV4) ? *(const float4*)(W + e) : make_float4(0.f, 0.f, 0.f, 0.f);
            dst = g_Wbf + e;
        } else {
            size_t e = (i - nW4) * 4;
            v = *(const float4*)(A + e);
            dst = g_Abf + e;
        }
        uint2 hp;
        hp.x = packbf2(v.x, v.y);
        hp.y = packbf2(v.z, v.w);
        *(uint2*)dst = hp;
    }
}

// ---------------- stage loader: 128x64 A + 128x64 B (bf16) ----------------
__device__ __forceinline__ void load_stage(uint32_t sb, int buf, int m0, int n0,
                                           int kt, int tid) {
    uint32_t base = sb + buf * STG_BYTES;
    #pragma unroll
    for (int i = 0; i < 4; i++) {
        int id = tid + i * 256;                  // 0..1023
        int row = id >> 3, c = id & 7;           // 128 rows x 8 x 16B
        uint32_t so = sw128(row * 128 + c * 16);
        cp16(base + so,       g_Abf + (size_t)(m0 + row) * KDIM + kt + c * 8);
        cp16(base + R_B + so, g_Wbf + (size_t)(n0 + row) * KDIM + kt + c * 8);
    }
}

// ---------------- stage compute: 4 x k16, 64 HMMA per warp ----------------
__device__ __forceinline__ void compute_stage(uint32_t sb, int buf, int lane,
                                              int wm, int wn, float acc[4][4][4]) {
    uint32_t base = sb + buf * STG_BYTES;
    #pragma unroll
    for (int kk = 0; kk < 4; kk++) {
        uint32_t ah[4][4], bh[2][4];
        #pragma unroll
        for (int mi = 0; mi < 4; mi++) {
            int row = wm * 64 + mi * 16 + (lane & 15);
            uint32_t off = sw128(row * 128 + kk * 32 + ((lane >> 4) & 1) * 16);
            ldsm_x4(ah[mi], base + off);
        }
        #pragma unroll
        for (int bi = 0; bi < 2; bi++) {
            int row = wn * 32 + bi * 16 + (lane & 7) + ((lane >> 4) & 1) * 8;
            uint32_t off = sw128(row * 128 + kk * 32 + ((lane >> 3) & 1) * 16);
            ldsm_x4(bh[bi], base + R_B + off);
        }
        #pragma unroll
        for (int mi = 0; mi < 4; mi++)
            #pragma unroll
            for (int ni = 0; ni < 4; ni++)
                mma16816(acc[mi][ni], ah[mi], &bh[ni >> 1][(ni & 1) * 2]);
    }
}

// ---------------- main GEMM + fused top-2 epilogue ----------------
__global__ __launch_bounds__(256, 2)
void gemm_hmma_top2(const float* __restrict__ br, const float* __restrict__ gum) {
    extern __shared__ char smem[];
    const uint32_t sb = smem_u32(smem);
    const int tid  = threadIdx.x;
    const int lane = tid & 31;
    const int wid  = tid >> 5;
    const int wm   = wid & 1;           // 2 warps over m
    const int wn   = wid >> 1;          // 4 warps over n
    const int m0   = blockIdx.x * BM;   // x fastest: 8 m-CTAs share B tile in L2
    const int nt   = blockIdx.y;
    const int n0   = nt * BN;

    float acc[4][4][4];
    #pragma unroll
    for (int mi = 0; mi < 4; mi++)
        #pragma unroll
        for (int ni = 0; ni < 4; ni++)
            #pragma unroll
            for (int j = 0; j < 4; j++) acc[mi][ni][j] = 0.f;

    #pragma unroll
    for (int s = 0; s < NSTG - 1; s++) {
        load_stage(sb, s, m0, n0, s * BK, tid);
        cp_commit();
    }
    for (int k = 0; k < NKT; k++) {
        int pf = k + NSTG - 1;
        if (pf < NKT) load_stage(sb, pf % NSTG, m0, n0, pf * BK, tid);
        cp_commit();
        cp_wait<NSTG - 1>();
        __syncthreads();
        compute_stage(sb, k % NSTG, lane, wm, wn, acc);
        __syncthreads();
    }

    // ---- epilogue: +br +gumbel, per-row top-2 ----
    const int g = lane >> 2, t = lane & 3;
    // reuse stage smem: per row, per n-warp: {v1,i1,v2,i2}
    float* pv = (float*)smem;                   // [128][4][2] interleaved below
    int*   pidx = (int*)(smem + 8192);

    float2 brv[4];
    bool valid[4];
    #pragma unroll
    for (int ni = 0; ni < 4; ni++) {
        int col = wn * 32 + ni * 8 + 2 * t;
        valid[ni] = (n0 + col) < VOC;           // pairs all-or-none (VOC even)
        brv[ni] = valid[ni] ? *(const float2*)(br + n0 + col) : make_float2(0.f, 0.f);
    }

    #pragma unroll
    for (int mi = 0; mi < 4; mi++) {
        #pragma unroll
        for (int h = 0; h < 2; h++) {
            int rl = wm * 64 + mi * 16 + g + h * 8;
            const float* gr = gum + (size_t)(m0 + rl) * VOC + n0;
            float m1 = -FLT_MAX, m2 = -FLT_MAX;
            int   i1 = 0x7fffffff, i2 = 0x7fffffff;
            #pragma unroll
            for (int ni = 0; ni < 4; ni++) {
                if (valid[ni]) {
                    int col = wn * 32 + ni * 8 + 2 * t;
                    float2 gg = *(const float2*)(gr + col);
                    float v0 = acc[mi][ni][h * 2 + 0] + brv[ni].x + gg.x;
                    float v1 = acc[mi][ni][h * 2 + 1] + brv[ni].y + gg.y;
                    top2_merge(v0, n0 + col,     m1, i1, m2, i2);
                    top2_merge(v1, n0 + col + 1, m1, i1, m2, i2);
                }
            }
            #pragma unroll
            for (int s = 1; s < 4; s <<= 1) {
                float o1 = __shfl_xor_sync(0xffffffffu, m1, s);
                int   oi1 = __shfl_xor_sync(0xffffffffu, i1, s);
                float o2 = __shfl_xor_sync(0xffffffffu, m2, s);
                int   oi2 = __shfl_xor_sync(0xffffffffu, i2, s);
                top2_merge(o1, oi1, m1, i1, m2, i2);
                top2_merge(o2, oi2, m1, i1, m2, i2);
            }
            if (t == 0) {
                pv[(rl * 4 + wn) * 2 + 0] = m1;
                pv[(rl * 4 + wn) * 2 + 1] = m2;
                pidx[(rl * 4 + wn) * 2 + 0] = i1;
                pidx[(rl * 4 + wn) * 2 + 1] = i2;
            }
        }
    }
    __syncthreads();
    if (tid < BM) {
        float m1 = -FLT_MAX, m2 = -FLT_MAX;
        int   i1 = 0x7fffffff, i2 = 0x7fffffff;
        #pragma unroll
        for (int w = 0; w < 4; w++) {           // ascending col warps
            top2_merge(pv[(tid * 4 + w) * 2 + 0], pidx[(tid * 4 + w) * 2 + 0], m1, i1, m2, i2);
            top2_merge(pv[(tid * 4 + w) * 2 + 1], pidx[(tid * 4 + w) * 2 + 1], m1, i1, m2, i2);
        }
        size_t o = (size_t)(m0 + tid) * NT2 + nt;
        g_p1v[o] = m1; g_p1i[o] = i1;
        g_p2v[o] = m2; g_p2i[o] = i2;
    }
}

// ---------------- rescue + per-token contrib: 1 warp per token ----------------
__global__ __launch_bounds__(256)
void rescue_contrib(const float* __restrict__ A,    // fp32 [1024,768]
                    const float* __restrict__ Wr,   // fp32 [21128,768]
                    const float* __restrict__ br,
                    const float* __restrict__ gum,
                    const float* __restrict__ sim,
                    const int* __restrict__ ids,
                    const void* __restrict__ mask) {
    __shared__ int s_cand[8][64];
    __shared__ int s_cnt[8];
    const int w    = threadIdx.x >> 5;
    const int lane = threadIdx.x & 31;
    const int tok  = blockIdx.x * 8 + w;   // grid 128 * 8 warps = 1024 tokens

    // 1) global bf16 argmax over tile top-1s (min-idx tie-break)
    float M = -FLT_MAX;
    int Mi = 0x7fffffff;
    const size_t base = (size_t)tok * NT2;
    for (int n = lane; n < NT2; n += 32) {
        float v = g_p1v[base + n];
        int   i = g_p1i[base + n];
        if (v > M || (v == M && i < Mi)) { M = v; Mi = i; }
    }
    #pragma unroll
    for (int s = 16; s > 0; s >>= 1) {
        float ov = __shfl_xor_sync(0xffffffffu, M, s);
        int   oi = __shfl_xor_sync(0xffffffffu, Mi, s);
        if (ov > M || (ov == M && oi < Mi)) { M = ov; Mi = oi; }
    }

    // 2) candidates within THETA of M
    if (lane == 0) s_cnt[w] = 0;
    __syncwarp();
    const float thr = M - THETA;
    for (int n = lane; n < NT2; n += 32) {
        float v1 = g_p1v[base + n]; int i1 = g_p1i[base + n];
        float v2 = g_p2v[base + n]; int i2 = g_p2i[base + n];
        if (v1 > thr && i1 != Mi) {
            int p = atomicAdd(&s_cnt[w], 1);
            if (p < 63) s_cand[w][p] = i1;
        }
        if (v2 > thr && i2 != Mi && i2 != 0x7fffffff) {
            int p = atomicAdd(&s_cnt[w], 1);
            if (p < 63) s_cand[w][p] = i2;
        }
    }
    __syncwarp();
    int ncand = min(s_cnt[w], 63);

    int besti = Mi;
    if (ncand > 0) {
        // exact fp32 rescore of incumbent + candidates
        float ar[24];
        #pragma unroll
        for (int j = 0; j < 24; j++)
            ar[j] = A[(size_t)tok * KDIM + j * 32 + lane];

        float bestv = -FLT_MAX;
        besti = 0x7fffffff;
        for (int cix = -1; cix < ncand; cix++) {
            int c = (cix < 0) ? Mi : s_cand[w][cix];
            const float* wrow = Wr + (size_t)c * KDIM;
            float s = 0.f;
            #pragma unroll
            for (int j = 0; j < 24; j++)
                s = fmaf(ar[j], wrow[j * 32 + lane], s);
            #pragma unroll
            for (int sh = 16; sh > 0; sh >>= 1)
                s += __shfl_xor_sync(0xffffffffu, s, sh);
            if (lane == 0) {
                float sc = s + br[c] + gum[(size_t)tok * VOC + c];
                if (sc > bestv || (sc == bestv && c < besti)) { bestv = sc; besti = c; }
            }
        }
        besti = __shfl_sync(0xffffffffu, besti, 0);
    }

    // 3) contrib
    if (lane == 0) {
        const int id = ids[tok];
        const int kind = g_mask_kind;
        bool ch;
        if (kind == 1)      ch = ((const int*)mask)[id] != 0;
        else if (kind == 2) ch = ((const float*)mask)[id] != 0.0f;
        else                ch = ((const unsigned char*)mask)[id] != 0;
        g_contrib[tok] = ch ? (1.0f - sim[(size_t)id * VOC + besti]) : 0.0f;
    }
}

// ---------------- final deterministic sum ----------------
__global__ void final_sum(float* __restrict__ out, int out_size) {
    __shared__ float red[1024];
    const int t = threadIdx.x;
    red[t] = g_contrib[t];
    __syncthreads();
    for (int s = 512; s > 0; s >>= 1) {
        if (t < s) red[t] += red[t + s];
        __syncthreads();
    }
    if (t == 0) {
        float L = red[0] * (1.0f / 1024.0f);
        for (int k = 0; k < out_size; k++) out[k] = L;
    }
}

extern "C" void kernel_launch(void* const* d_in, const int* in_sizes, int n_in,
                              void* d_out, int out_size) {
    const float* seq  = (const float*)d_in[0];   // [8,128,768]
    const float* Wr   = (const float*)d_in[1];   // [21128,768]
    const float* br   = (const float*)d_in[2];   // [21128]
    const float* sim  = (const float*)d_in[3];   // [21128,21128]
    const float* gum  = (const float*)d_in[4];   // [8,128,21128]
    const int*   ids  = (const int*)d_in[5];     // [8,128]
    const void*  mask = d_in[6];                 // [21128] bool-ish

    static bool attr_set = false;
    if (!attr_set) {
        cudaFuncSetAttribute(gemm_hmma_top2,
                             cudaFuncAttributeMaxDynamicSharedMemorySize, SM_TOTAL_G);
        attr_set = true;
    }

    probe_mask_kind<<<1, 1024>>>((const unsigned char*)mask);
    convert_bf16<<<2048, 256>>>(seq, Wr);

    dim3 grid(M_TOK / BM, NT2);   // (8, 166); x fastest -> B tile shared in L2
    gemm_hmma_top2<<<grid, 256, SM_TOTAL_G>>>(br, gum);

    rescue_contrib<<<128, 256>>>(seq, Wr, br, gum, sim, ids, mask);
    final_sum<<<1, 1024>>>((float*)d_out, out_size);
}